// round 1
// baseline (speedup 1.0000x reference)
#include <cuda_runtime.h>
#include <cstdint>

// ---------------- problem dims ----------------
#define BB 8
#define NN 256
#define NI 36
#define SS 64
#define IN_D 1024
#define QUE_D 1024
#define IMG_D 2048
#define SEM_D 512
#define PP 512          // P_IMG == P_SEM == GATE == 512
#define CATD 1536
#define OUTD 1024
#define ROWS (BB*NN)    // 2048

// ---------------- scratch (device globals; no allocation allowed) ----------------
__device__ float g_qproj_img[BB*PP];
__device__ float g_qproj_sem[BB*PP];
__device__ float g_np_img[ROWS*PP];
__device__ float g_np_sem[ROWS*PP];
__device__ float g_ip[BB*NI*PP];
__device__ float g_sp[BB*SS*PP];
__device__ float g_img_ctx[ROWS*IMG_D];
__device__ float g_sem_ctx[ROWS*SEM_D];
__device__ float g_cat[ROWS*CATD];
__device__ float g_gcat[ROWS*CATD];

// ---------------- helpers ----------------
__device__ __forceinline__ float tanh_fast(float x) {
    float y;
    asm("tanh.approx.f32 %0, %1;" : "=f"(y) : "f"(x));
    return y;
}
__device__ __forceinline__ float sigmoid_fast(float x) {
    return 1.0f / (1.0f + __expf(-x));
}

// ---------------- tiny GEMM for que projection: out[b,j] = bias[j] + que[b,:] @ Wsub[:,j]
// grid (PP/128, BB), 128 threads
__global__ void qproj_kernel(const float* __restrict__ que,
                             const float* __restrict__ Wsub,   // [QUE_D, PP] row-major
                             const float* __restrict__ bias,
                             float* __restrict__ out) {
    int b = blockIdx.y;
    int j = blockIdx.x * 128 + threadIdx.x;
    const float* q = que + b * QUE_D;
    float acc = bias[j];
#pragma unroll 4
    for (int k = 0; k < QUE_D; k++) {
        acc += q[k] * Wsub[(size_t)k * PP + j];
    }
    out[b * PP + j] = acc;
}

// ---------------- main SGEMM: C[M,N] = A[M,K] @ W[K,N] (+ epilogue) ----------------
// MODE 0: C = acc + bias[col]
// MODE 1: C = acc + extra[(row>>8)*lde + col]          (per-batch que-proj add, bias folded in)
// MODE 2: C = sigmoid(acc + bias[col]) * extra[row*lde + col]   (gate)
// Tiles: 64(M) x 128(N) x 16(K), 256 threads, 4x8 per thread.
// Requirements: K % 16 == 0, N % 128 == 0 (all call sites satisfy), M guarded.
template <int MODE>
__global__ __launch_bounds__(256)
void gemm_kernel(const float* __restrict__ A, int lda,
                 const float* __restrict__ W, int ldb,
                 const float* __restrict__ bias,
                 const float* __restrict__ extra, int lde,
                 float* __restrict__ C, int ldc,
                 int M, int K) {
    __shared__ float As[16][64];
    __shared__ float Bs[16][128];

    const int tid = threadIdx.x;
    const int tx = tid & 15;          // col group
    const int ty = tid >> 4;          // row group
    const int m0 = blockIdx.y * 64;
    const int n0 = blockIdx.x * 128;

    // load mapping
    const int arow = tid >> 2;            // 0..63
    const int acol = (tid & 3) * 4;       // 0,4,8,12
    const int brow = tid >> 4;            // 0..15
    const int bcol = (tid & 15) * 8;      // 0..120

    const bool arow_ok = (m0 + arow) < M;
    const float* Aptr = A + (size_t)(m0 + arow) * lda + acol;
    const float* Wptr = W + (size_t)brow * ldb + n0 + bcol;

    float acc[4][8];
#pragma unroll
    for (int i = 0; i < 4; i++)
#pragma unroll
        for (int j = 0; j < 8; j++) acc[i][j] = 0.0f;

    for (int k0 = 0; k0 < K; k0 += 16) {
        float4 av = arow_ok ? *(const float4*)(Aptr + k0)
                            : make_float4(0.f, 0.f, 0.f, 0.f);
        As[acol + 0][arow] = av.x;
        As[acol + 1][arow] = av.y;
        As[acol + 2][arow] = av.z;
        As[acol + 3][arow] = av.w;

        float4 bv0 = *(const float4*)(Wptr + (size_t)k0 * ldb);
        float4 bv1 = *(const float4*)(Wptr + (size_t)k0 * ldb + 4);
        *(float4*)&Bs[brow][bcol]     = bv0;
        *(float4*)&Bs[brow][bcol + 4] = bv1;
        __syncthreads();

#pragma unroll
        for (int kk = 0; kk < 16; kk++) {
            float a[4], b[8];
            *(float4*)a       = *(const float4*)&As[kk][ty * 4];
            *(float4*)b       = *(const float4*)&Bs[kk][tx * 8];
            *(float4*)(b + 4) = *(const float4*)&Bs[kk][tx * 8 + 4];
#pragma unroll
            for (int i = 0; i < 4; i++)
#pragma unroll
                for (int j = 0; j < 8; j++)
                    acc[i][j] = fmaf(a[i], b[j], acc[i][j]);
        }
        __syncthreads();
    }

    // epilogue
#pragma unroll
    for (int i = 0; i < 4; i++) {
        int r = m0 + ty * 4 + i;
        if (r >= M) continue;
#pragma unroll
        for (int j = 0; j < 8; j++) {
            int c = n0 + tx * 8 + j;
            float v;
            if (MODE == 0) {
                v = acc[i][j] + bias[c];
            } else if (MODE == 1) {
                v = acc[i][j] + extra[(size_t)(r >> 8) * lde + c];
            } else { // MODE == 2
                v = sigmoid_fast(acc[i][j] + bias[c]) * extra[(size_t)r * lde + c];
            }
            C[(size_t)r * ldc + c] = v;
        }
    }
}

// ---------------- fused attention (image): per (b,n) block ----------------
// logits[k] = sum_p tanh(np[row,p] + ip[b,k,p]) * w[p]; softmax over k; ctx = att @ img
__global__ __launch_bounds__(256)
void att_img_kernel(const float* __restrict__ np_, const float* __restrict__ ip,
                    const float* __restrict__ img, const float* __restrict__ w,
                    float* __restrict__ ctx) {
    __shared__ float s_np[PP];
    __shared__ float s_w[PP];
    __shared__ float s_log[64];
    __shared__ float s_att[64];

    const int row = blockIdx.x;
    const int b = row >> 8;
    const int tid = threadIdx.x;
    const int warp = tid >> 5, lane = tid & 31;

    for (int i = tid; i < PP; i += 256) {
        s_np[i] = np_[(size_t)row * PP + i];
        s_w[i]  = w[i];
    }
    __syncthreads();

    for (int k = warp; k < NI; k += 8) {
        const float* iprow = ip + (size_t)(b * NI + k) * PP;
        float acc = 0.0f;
#pragma unroll 4
        for (int i = lane; i < PP; i += 32) {
            float t = tanh_fast(s_np[i] + iprow[i]);
            acc = fmaf(t, s_w[i], acc);
        }
#pragma unroll
        for (int o = 16; o > 0; o >>= 1) acc += __shfl_xor_sync(0xffffffff, acc, o);
        if (lane == 0) s_log[k] = acc;
    }
    __syncthreads();

    if (warp == 0) {
        float v0 = (lane < NI) ? s_log[lane] : -1e30f;
        float v1 = (lane + 32 < NI) ? s_log[lane + 32] : -1e30f;
        float m = fmaxf(v0, v1);
#pragma unroll
        for (int o = 16; o > 0; o >>= 1) m = fmaxf(m, __shfl_xor_sync(0xffffffff, m, o));
        float e0 = (lane < NI) ? __expf(v0 - m) : 0.0f;
        float e1 = (lane + 32 < NI) ? __expf(v1 - m) : 0.0f;
        float s = e0 + e1;
#pragma unroll
        for (int o = 16; o > 0; o >>= 1) s += __shfl_xor_sync(0xffffffff, s, o);
        float inv = 1.0f / s;
        if (lane < NI) s_att[lane] = e0 * inv;
        if (lane + 32 < NI) s_att[lane + 32] = e1 * inv;
    }
    __syncthreads();

    const float* imgb = img + (size_t)b * NI * IMG_D;
    for (int d = tid; d < IMG_D; d += 256) {
        float acc = 0.0f;
#pragma unroll
        for (int k = 0; k < NI; k++)
            acc = fmaf(s_att[k], imgb[(size_t)k * IMG_D + d], acc);
        ctx[(size_t)row * IMG_D + d] = acc;
    }
}

// ---------------- fused attention (semantic): per (b,n) block ----------------
__global__ __launch_bounds__(256)
void att_sem_kernel(const float* __restrict__ np_, const float* __restrict__ sp,
                    const float* __restrict__ sem, const float* __restrict__ w,
                    float* __restrict__ ctx) {
    __shared__ float s_np[PP];
    __shared__ float s_w[PP];
    __shared__ float s_log[64];
    __shared__ float s_att[64];

    const int row = blockIdx.x;
    const int b = row >> 8;
    const int tid = threadIdx.x;
    const int warp = tid >> 5, lane = tid & 31;

    for (int i = tid; i < PP; i += 256) {
        s_np[i] = np_[(size_t)row * PP + i];
        s_w[i]  = w[i];
    }
    __syncthreads();

    for (int k = warp; k < SS; k += 8) {
        const float* sprow = sp + (size_t)(b * SS + k) * PP;
        float acc = 0.0f;
#pragma unroll 4
        for (int i = lane; i < PP; i += 32) {
            float t = tanh_fast(s_np[i] + sprow[i]);
            acc = fmaf(t, s_w[i], acc);
        }
#pragma unroll
        for (int o = 16; o > 0; o >>= 1) acc += __shfl_xor_sync(0xffffffff, acc, o);
        if (lane == 0) s_log[k] = acc;
    }
    __syncthreads();

    if (warp == 0) {
        float v0 = s_log[lane];
        float v1 = s_log[lane + 32];
        float m = fmaxf(v0, v1);
#pragma unroll
        for (int o = 16; o > 0; o >>= 1) m = fmaxf(m, __shfl_xor_sync(0xffffffff, m, o));
        float e0 = __expf(v0 - m);
        float e1 = __expf(v1 - m);
        float s = e0 + e1;
#pragma unroll
        for (int o = 16; o > 0; o >>= 1) s += __shfl_xor_sync(0xffffffff, s, o);
        float inv = 1.0f / s;
        s_att[lane] = e0 * inv;
        s_att[lane + 32] = e1 * inv;
    }
    __syncthreads();

    const float* semb = sem + (size_t)b * SS * SEM_D;
    for (int d = tid; d < SEM_D; d += 256) {
        float acc = 0.0f;
#pragma unroll
        for (int k = 0; k < SS; k++)
            acc = fmaf(s_att[k], semb[(size_t)k * SEM_D + d], acc);
        ctx[(size_t)row * SEM_D + d] = acc;
    }
}

// ---------------- launch ----------------
extern "C" void kernel_launch(void* const* d_in, const int* in_sizes, int n_in,
                              void* d_out, int out_size) {
    const float* h      = (const float*)d_in[0];
    const float* img    = (const float*)d_in[1];
    const float* sem    = (const float*)d_in[2];
    const float* que    = (const float*)d_in[3];
    const float* W_cif  = (const float*)d_in[4];
    const float* b_cif  = (const float*)d_in[5];
    const float* W_cii  = (const float*)d_in[6];
    const float* b_cii  = (const float*)d_in[7];
    const float* w_ia   = (const float*)d_in[8];
    // d_in[9]  = b_ia  (scalar; softmax-invariant, unused)
    const float* W_csf  = (const float*)d_in[10];
    const float* b_csf  = (const float*)d_in[11];
    const float* W_csn  = (const float*)d_in[12];
    const float* b_csn  = (const float*)d_in[13];
    const float* w_sa   = (const float*)d_in[14];
    // d_in[15] = b_sa  (scalar; softmax-invariant, unused)
    const float* W_ig   = (const float*)d_in[16];
    const float* b_ig   = (const float*)d_in[17];
    const float* W_sg   = (const float*)d_in[18];
    const float* b_sg   = (const float*)d_in[19];
    const float* W_fg   = (const float*)d_in[20];
    const float* b_fg   = (const float*)d_in[21];
    const float* W_gate = (const float*)d_in[22];
    const float* b_gate = (const float*)d_in[23];
    const float* W_out  = (const float*)d_in[24];
    const float* b_out  = (const float*)d_in[25];
    float* out = (float*)d_out;

    float *qpi, *qps, *npi, *nps, *ipb, *spb, *ictx, *sctx, *cat, *gcat;
    cudaGetSymbolAddress((void**)&qpi,  g_qproj_img);
    cudaGetSymbolAddress((void**)&qps,  g_qproj_sem);
    cudaGetSymbolAddress((void**)&npi,  g_np_img);
    cudaGetSymbolAddress((void**)&nps,  g_np_sem);
    cudaGetSymbolAddress((void**)&ipb,  g_ip);
    cudaGetSymbolAddress((void**)&spb,  g_sp);
    cudaGetSymbolAddress((void**)&ictx, g_img_ctx);
    cudaGetSymbolAddress((void**)&sctx, g_sem_ctx);
    cudaGetSymbolAddress((void**)&cat,  g_cat);
    cudaGetSymbolAddress((void**)&gcat, g_gcat);

    // que projections (bias folded in): qproj = que @ W_c*f[IN_D:, :] + b
    qproj_kernel<<<dim3(PP / 128, BB), 128>>>(que, W_cif + (size_t)IN_D * PP, b_cif, qpi);
    qproj_kernel<<<dim3(PP / 128, BB), 128>>>(que, W_csf + (size_t)IN_D * PP, b_csf, qps);

    // np = h @ W_c*f[:IN_D, :] + qproj[b]
    gemm_kernel<1><<<dim3(PP / 128, ROWS / 64), 256>>>(h, IN_D, W_cif, PP, nullptr, qpi, PP, npi, PP, ROWS, IN_D);
    gemm_kernel<1><<<dim3(PP / 128, ROWS / 64), 256>>>(h, IN_D, W_csf, PP, nullptr, qps, PP, nps, PP, ROWS, IN_D);

    // ip = img @ W_cii + b_cii   [288, 512]
    gemm_kernel<0><<<dim3(PP / 128, (BB * NI + 63) / 64), 256>>>(img, IMG_D, W_cii, PP, b_cii, nullptr, 0, ipb, PP, BB * NI, IMG_D);
    // sp = sem @ W_csn + b_csn   [512, 512]
    gemm_kernel<0><<<dim3(PP / 128, (BB * SS) / 64), 256>>>(sem, SEM_D, W_csn, PP, b_csn, nullptr, 0, spb, PP, BB * SS, SEM_D);

    // fused attention
    att_img_kernel<<<ROWS, 256>>>(npi, ipb, img, w_ia, ictx);
    att_sem_kernel<<<ROWS, 256>>>(nps, spb, sem, w_sa, sctx);

    // fusion projections into cat = [f | i | s]
    gemm_kernel<0><<<dim3(PP / 128, ROWS / 64), 256>>>(h,    IN_D,  W_fg, PP, b_fg, nullptr, 0, cat,        CATD, ROWS, IN_D);
    gemm_kernel<0><<<dim3(PP / 128, ROWS / 64), 256>>>(ictx, IMG_D, W_ig, PP, b_ig, nullptr, 0, cat + PP,   CATD, ROWS, IMG_D);
    gemm_kernel<0><<<dim3(PP / 128, ROWS / 64), 256>>>(sctx, SEM_D, W_sg, PP, b_sg, nullptr, 0, cat + 2*PP, CATD, ROWS, SEM_D);

    // gcat = sigmoid(cat @ W_gate + b_gate) * cat
    gemm_kernel<2><<<dim3(CATD / 128, ROWS / 64), 256>>>(cat, CATD, W_gate, CATD, b_gate, cat, CATD, gcat, CATD, ROWS, CATD);

    // out = gcat @ W_out + b_out
    gemm_kernel<0><<<dim3(OUTD / 128, ROWS / 64), 256>>>(gcat, CATD, W_out, OUTD, b_out, nullptr, 0, out, OUTD, ROWS, CATD);
}

// round 3
// speedup vs baseline: 2.3542x; 2.3542x over previous
#include <cuda_runtime.h>
#include <cstdint>

// ---------------- problem dims ----------------
#define BB 8
#define NN 256
#define NI 36
#define SS 64
#define IN_D 1024
#define QUE_D 1024
#define IMG_D 2048
#define SEM_D 512
#define PP 512
#define CATD 1536
#define OUTD 1024
#define ROWS (BB*NN)

// ---------------- scratch ----------------
__device__ float g_qproj_img[BB*PP];
__device__ float g_qproj_sem[BB*PP];
__device__ float g_np_img[ROWS*PP];
__device__ float g_np_sem[ROWS*PP];
__device__ float g_ip[BB*NI*PP];
__device__ float g_sp[BB*SS*PP];
__device__ float g_img_ctx[ROWS*IMG_D];
__device__ float g_sem_ctx[ROWS*SEM_D];
__device__ float g_cat[ROWS*CATD];
__device__ float g_gcat[ROWS*CATD];
__device__ float g_Wcif_t[PP*IN_D];
__device__ float g_Wcsf_t[PP*IN_D];
__device__ float g_Wcii_t[PP*IMG_D];
__device__ float g_Wcsn_t[PP*SEM_D];
__device__ float g_Wig_t[PP*IMG_D];
__device__ float g_Wsg_t[PP*SEM_D];
__device__ float g_Wfg_t[PP*IN_D];
__device__ float g_Wgate_t[CATD*CATD];
__device__ float g_Wout_t[OUTD*CATD];

// ---------------- helpers ----------------
__device__ __forceinline__ float tanh_fast(float x) {
    float y;
    asm("tanh.approx.f32 %0, %1;" : "=f"(y) : "f"(x));
    return y;
}
__device__ __forceinline__ float sigmoid_fast(float x) {
    return 1.0f / (1.0f + __expf(-x));
}
__device__ __forceinline__ uint32_t f2tf(float x) {
    uint32_t r;
    asm("cvt.rna.tf32.f32 %0, %1;" : "=r"(r) : "f"(x));
    return r;
}
__device__ __forceinline__ void mma8(float* c, const uint32_t* a, uint32_t b0, uint32_t b1) {
    asm volatile(
        "mma.sync.aligned.m16n8k8.row.col.f32.tf32.tf32.f32 "
        "{%0,%1,%2,%3}, {%4,%5,%6,%7}, {%8,%9}, {%0,%1,%2,%3};"
        : "+f"(c[0]), "+f"(c[1]), "+f"(c[2]), "+f"(c[3])
        : "r"(a[0]), "r"(a[1]), "r"(a[2]), "r"(a[3]), "r"(b0), "r"(b1));
}

// ---------------- batched tf32 MMA GEMM ----------------
// C[M,N] = A[M,K] @ Bt[N,K]^T, epilogue by mode:
//  0: + bias[col]
//  1: + extra[(row>>8)*lde + col]
//  2: sigmoid(acc + bias[col]) * extra[row*lde + col]
// CTA tile 128x128, warp tile 64x32 (2x4 warps), K stage 32, double buffered.
// Smem fragment layout with XOR chunk swizzle: conflict-free STS.128 and LDS.32.
struct TaskDesc {
    const float* A; const float* Bt; const float* bias; const float* extra;
    float* C; int lda, ldb, lde, ldc, M, K, mode;
};

__global__ __launch_bounds__(256)
void mma_gemm(TaskDesc t0, TaskDesc t1, TaskDesc t2) {
    TaskDesc T = (blockIdx.z == 0) ? t0 : (blockIdx.z == 1) ? t1 : t2;
    const int m0 = blockIdx.y * 128;
    if (m0 >= T.M) return;
    const int n0 = blockIdx.x * 128;

    extern __shared__ float sm[];   // 2 stages x 8192 floats (A 4096 | B 4096)

    const int tid = threadIdx.x;
    const int lane = tid & 31;
    const int wid = tid >> 5;
    const int wr = wid >> 2;        // 0..1
    const int wc = wid & 3;         // 0..3

    // ---- loader constants (per thread) ----
    const int kq   = tid & 7;       // float4 index along k (0..7 -> k = kq*4)
    const int mrow = tid >> 3;      // base row 0..31 (rows mrow + 32*s)
    const int kk_w = kq >> 1;       // k8-step 0..3
    const int regA = ((mrow >> 3) & 1) + ((kq & 1) << 1);
    const int regB = kq & 1;
    const int chunk_w = (mrow & 7) ^ kq;   // XOR-swizzled 16B-chunk index

    const float* Ab = T.A + (size_t)(m0 + mrow) * T.lda + kq * 4;
    const float* Bb = T.Bt + (size_t)(n0 + mrow) * T.ldb + kq * 4;
    bool mok[4];
#pragma unroll
    for (int s = 0; s < 4; s++) mok[s] = (m0 + mrow + 32 * s) < T.M;

    float acc[4][4][4];
#pragma unroll
    for (int i = 0; i < 4; i++)
#pragma unroll
        for (int t = 0; t < 4; t++)
#pragma unroll
            for (int r = 0; r < 4; r++) acc[i][t][r] = 0.0f;

    float4 avs[4], bvs[4];

    // stage-0 load
#pragma unroll
    for (int s = 0; s < 4; s++) {
        avs[s] = mok[s] ? *(const float4*)(Ab + (size_t)s * 32 * T.lda)
                        : make_float4(0.f, 0.f, 0.f, 0.f);
        bvs[s] = *(const float4*)(Bb + (size_t)s * 32 * T.ldb);
    }
    {
        float* base = sm;
#pragma unroll
        for (int s = 0; s < 4; s++) {
            int mt = (mrow >> 4) + 2 * s;
            float* pa = base + (((mt * 4 + kk_w) * 4 + regA) << 5) + chunk_w * 4;
            float4 va;
            va.x = __uint_as_float(f2tf(avs[s].x)); va.y = __uint_as_float(f2tf(avs[s].y));
            va.z = __uint_as_float(f2tf(avs[s].z)); va.w = __uint_as_float(f2tf(avs[s].w));
            *(float4*)pa = va;
            int nt = (mrow >> 3) + 4 * s;
            float* pb = base + 4096 + (((nt * 4 + kk_w) * 2 + regB) << 5) + chunk_w * 4;
            float4 vb;
            vb.x = __uint_as_float(f2tf(bvs[s].x)); vb.y = __uint_as_float(f2tf(bvs[s].y));
            vb.z = __uint_as_float(f2tf(bvs[s].z)); vb.w = __uint_as_float(f2tf(bvs[s].w));
            *(float4*)pb = vb;
        }
    }
    __syncthreads();

    const int S = T.K >> 5;
    for (int sidx = 0; sidx < S; sidx++) {
        // prefetch next stage into registers
        if (sidx + 1 < S) {
            int k0 = (sidx + 1) << 5;
#pragma unroll
            for (int s = 0; s < 4; s++) {
                avs[s] = mok[s] ? *(const float4*)(Ab + (size_t)s * 32 * T.lda + k0)
                                : make_float4(0.f, 0.f, 0.f, 0.f);
                bvs[s] = *(const float4*)(Bb + (size_t)s * 32 * T.ldb + k0);
            }
        }
        // compute current stage
        {
            const float* base = sm + (size_t)(sidx & 1) * 8192;
#pragma unroll
            for (int kk = 0; kk < 4; kk++) {
                uint32_t a[4][4], b[4][2];
#pragma unroll
                for (int i = 0; i < 4; i++) {
                    int mt = wr * 4 + i;
#pragma unroll
                    for (int r = 0; r < 4; r++) {
                        int chunk = (lane >> 2) ^ (kk * 2 + (r >> 1));
                        a[i][r] = __float_as_uint(
                            base[(((mt * 4 + kk) * 4 + r) << 5) + chunk * 4 + (lane & 3)]);
                    }
                }
#pragma unroll
                for (int t = 0; t < 4; t++) {
                    int nt = wc * 4 + t;
#pragma unroll
                    for (int r = 0; r < 2; r++) {
                        int chunk = (lane >> 2) ^ (kk * 2 + r);
                        b[t][r] = __float_as_uint(
                            base[4096 + (((nt * 4 + kk) * 2 + r) << 5) + chunk * 4 + (lane & 3)]);
                    }
                }
#pragma unroll
                for (int i = 0; i < 4; i++)
#pragma unroll
                    for (int t = 0; t < 4; t++)
                        mma8(acc[i][t], a[i], b[t][0], b[t][1]);
            }
        }
        // store next stage
        if (sidx + 1 < S) {
            float* base = sm + (size_t)((sidx + 1) & 1) * 8192;
#pragma unroll
            for (int s = 0; s < 4; s++) {
                int mt = (mrow >> 4) + 2 * s;
                float* pa = base + (((mt * 4 + kk_w) * 4 + regA) << 5) + chunk_w * 4;
                float4 va;
                va.x = __uint_as_float(f2tf(avs[s].x)); va.y = __uint_as_float(f2tf(avs[s].y));
                va.z = __uint_as_float(f2tf(avs[s].z)); va.w = __uint_as_float(f2tf(avs[s].w));
                *(float4*)pa = va;
                int nt = (mrow >> 3) + 4 * s;
                float* pb = base + 4096 + (((nt * 4 + kk_w) * 2 + regB) << 5) + chunk_w * 4;
                float4 vb;
                vb.x = __uint_as_float(f2tf(bvs[s].x)); vb.y = __uint_as_float(f2tf(bvs[s].y));
                vb.z = __uint_as_float(f2tf(bvs[s].z)); vb.w = __uint_as_float(f2tf(bvs[s].w));
                *(float4*)pb = vb;
            }
        }
        __syncthreads();
    }

    // ---- epilogue ----
#pragma unroll
    for (int i = 0; i < 4; i++) {
        int rbase = m0 + wr * 64 + i * 16 + (lane >> 2);
#pragma unroll
        for (int t = 0; t < 4; t++) {
            int cb = n0 + wc * 32 + t * 8 + 2 * (lane & 3);
#pragma unroll
            for (int hh = 0; hh < 2; hh++) {
                int r = rbase + 8 * hh;
                if (r >= T.M) continue;
                float c0 = acc[i][t][2 * hh], c1 = acc[i][t][2 * hh + 1];
                float2 v;
                if (T.mode == 0) {
                    float2 bs = *(const float2*)(T.bias + cb);
                    v = make_float2(c0 + bs.x, c1 + bs.y);
                } else if (T.mode == 1) {
                    float2 ev = *(const float2*)(T.extra + (size_t)(r >> 8) * T.lde + cb);
                    v = make_float2(c0 + ev.x, c1 + ev.y);
                } else {
                    float2 bs = *(const float2*)(T.bias + cb);
                    float2 ev = *(const float2*)(T.extra + (size_t)r * T.lde + cb);
                    v = make_float2(sigmoid_fast(c0 + bs.x) * ev.x,
                                    sigmoid_fast(c1 + bs.y) * ev.y);
                }
                *(float2*)(T.C + (size_t)r * T.ldc + cb) = v;
            }
        }
    }
}

// ---------------- weight transpose ----------------
__global__ void transpose_kernel(const float* __restrict__ in, float* __restrict__ out, int K, int N) {
    __shared__ float t[32][33];
    int n0 = blockIdx.x * 32, k0 = blockIdx.y * 32;
#pragma unroll
    for (int i = threadIdx.y; i < 32; i += 8)
        t[i][threadIdx.x] = in[(size_t)(k0 + i) * N + n0 + threadIdx.x];
    __syncthreads();
#pragma unroll
    for (int i = threadIdx.y; i < 32; i += 8)
        out[(size_t)(n0 + i) * K + k0 + threadIdx.x] = t[threadIdx.x][i];
}

// ---------------- que projection ----------------
__global__ void qproj_kernel(const float* __restrict__ que,
                             const float* __restrict__ Wsub,
                             const float* __restrict__ bias,
                             float* __restrict__ out) {
    int b = blockIdx.y;
    int j = blockIdx.x * 128 + threadIdx.x;
    const float* q = que + b * QUE_D;
    float acc = bias[j];
#pragma unroll 4
    for (int k = 0; k < QUE_D; k++) acc += q[k] * Wsub[(size_t)k * PP + j];
    out[b * PP + j] = acc;
}

// ---------------- fused attention: 8 rows per block ----------------
// logits[r][k] = sum_p tanh(np[row_r,p] + kp[b,k,p]) * w[p]; softmax over k;
// ctx[row_r] = att[r] @ kv[b]     (kv: [B, KN, D])
template <int KN, int D>
__global__ __launch_bounds__(256)
void att_kernel(const float* __restrict__ np_, const float* __restrict__ kp,
                const float* __restrict__ kv, const float* __restrict__ w,
                float* __restrict__ ctx) {
    __shared__ __align__(16) float s_w[PP];
    __shared__ float s_logit[8][64];
    __shared__ float s_att[8][64];

    const int g = blockIdx.x;
    const int b = g >> 5;
    const int r0 = (g & 31) * 8;
    const int tid = threadIdx.x;
    const int wid = tid >> 5, lane = tid & 31;

    for (int i = tid; i < PP; i += 256) s_w[i] = w[i];

    const int row = b * NN + r0 + wid;
    float4 npv[4];
    const float4* nr = (const float4*)(np_ + (size_t)row * PP);
#pragma unroll
    for (int i = 0; i < 4; i++) npv[i] = nr[lane + 32 * i];
    __syncthreads();

    // logits
    for (int k = 0; k < KN; k++) {
        const float4* kr = (const float4*)(kp + (size_t)(b * KN + k) * PP);
        float acc = 0.0f;
#pragma unroll
        for (int i = 0; i < 4; i++) {
            float4 kv4 = kr[lane + 32 * i];
            float4 w4 = ((const float4*)s_w)[lane + 32 * i];
            acc = fmaf(tanh_fast(npv[i].x + kv4.x), w4.x, acc);
            acc = fmaf(tanh_fast(npv[i].y + kv4.y), w4.y, acc);
            acc = fmaf(tanh_fast(npv[i].z + kv4.z), w4.z, acc);
            acc = fmaf(tanh_fast(npv[i].w + kv4.w), w4.w, acc);
        }
#pragma unroll
        for (int o = 16; o > 0; o >>= 1) acc += __shfl_xor_sync(0xffffffff, acc, o);
        if (lane == 0) s_logit[wid][k] = acc;
    }
    __syncwarp();

    // softmax (per warp, over KN)
    {
        float l0 = (lane < KN) ? s_logit[wid][lane] : -1e30f;
        float l1 = (lane + 32 < KN) ? s_logit[wid][lane + 32] : -1e30f;
        float m = fmaxf(l0, l1);
#pragma unroll
        for (int o = 16; o > 0; o >>= 1) m = fmaxf(m, __shfl_xor_sync(0xffffffff, m, o));
        float e0 = (lane < KN) ? __expf(l0 - m) : 0.0f;
        float e1 = (lane + 32 < KN) ? __expf(l1 - m) : 0.0f;
        float sum = e0 + e1;
#pragma unroll
        for (int o = 16; o > 0; o >>= 1) sum += __shfl_xor_sync(0xffffffff, sum, o);
        float inv = 1.0f / sum;
        s_att[wid][lane] = e0 * inv;
        if (lane + 32 < 64) s_att[wid][lane + 32] = e1 * inv;
    }
    __syncthreads();

    // context: 8 rows at once, value matrix read once per block
    const float4* kvb = (const float4*)(kv + (size_t)b * KN * D);
    for (int d4 = tid; d4 < D / 4; d4 += 256) {
        float4 a[8];
#pragma unroll
        for (int r = 0; r < 8; r++) a[r] = make_float4(0.f, 0.f, 0.f, 0.f);
        for (int k = 0; k < KN; k++) {
            float4 v = kvb[(size_t)k * (D / 4) + d4];
#pragma unroll
            for (int r = 0; r < 8; r++) {
                float at = s_att[r][k];
                a[r].x = fmaf(at, v.x, a[r].x);
                a[r].y = fmaf(at, v.y, a[r].y);
                a[r].z = fmaf(at, v.z, a[r].z);
                a[r].w = fmaf(at, v.w, a[r].w);
            }
        }
#pragma unroll
        for (int r = 0; r < 8; r++)
            *(float4*)(ctx + (size_t)(b * NN + r0 + r) * D + d4 * 4) = a[r];
    }
}

// ---------------- launch ----------------
extern "C" void kernel_launch(void* const* d_in, const int* in_sizes, int n_in,
                              void* d_out, int out_size) {
    const float* h      = (const float*)d_in[0];
    const float* img    = (const float*)d_in[1];
    const float* sem    = (const float*)d_in[2];
    const float* que    = (const float*)d_in[3];
    const float* W_cif  = (const float*)d_in[4];
    const float* b_cif  = (const float*)d_in[5];
    const float* W_cii  = (const float*)d_in[6];
    const float* b_cii  = (const float*)d_in[7];
    const float* w_ia   = (const float*)d_in[8];
    const float* W_csf  = (const float*)d_in[10];
    const float* b_csf  = (const float*)d_in[11];
    const float* W_csn  = (const float*)d_in[12];
    const float* b_csn  = (const float*)d_in[13];
    const float* w_sa   = (const float*)d_in[14];
    const float* W_ig   = (const float*)d_in[16];
    const float* b_ig   = (const float*)d_in[17];
    const float* W_sg   = (const float*)d_in[18];
    const float* b_sg   = (const float*)d_in[19];
    const float* W_fg   = (const float*)d_in[20];
    const float* b_fg   = (const float*)d_in[21];
    const float* W_gate = (const float*)d_in[22];
    const float* b_gate = (const float*)d_in[23];
    const float* W_out  = (const float*)d_in[24];
    const float* b_out  = (const float*)d_in[25];
    float* out = (float*)d_out;

    float *qpi, *qps, *npi, *nps, *ipb, *spb, *ictx, *sctx, *cat, *gcat;
    float *Wcif_t, *Wcsf_t, *Wcii_t, *Wcsn_t, *Wig_t, *Wsg_t, *Wfg_t, *Wgate_t, *Wout_t;
    cudaGetSymbolAddress((void**)&qpi,  g_qproj_img);
    cudaGetSymbolAddress((void**)&qps,  g_qproj_sem);
    cudaGetSymbolAddress((void**)&npi,  g_np_img);
    cudaGetSymbolAddress((void**)&nps,  g_np_sem);
    cudaGetSymbolAddress((void**)&ipb,  g_ip);
    cudaGetSymbolAddress((void**)&spb,  g_sp);
    cudaGetSymbolAddress((void**)&ictx, g_img_ctx);
    cudaGetSymbolAddress((void**)&sctx, g_sem_ctx);
    cudaGetSymbolAddress((void**)&cat,  g_cat);
    cudaGetSymbolAddress((void**)&gcat, g_gcat);
    cudaGetSymbolAddress((void**)&Wcif_t,  g_Wcif_t);
    cudaGetSymbolAddress((void**)&Wcsf_t,  g_Wcsf_t);
    cudaGetSymbolAddress((void**)&Wcii_t,  g_Wcii_t);
    cudaGetSymbolAddress((void**)&Wcsn_t,  g_Wcsn_t);
    cudaGetSymbolAddress((void**)&Wig_t,   g_Wig_t);
    cudaGetSymbolAddress((void**)&Wsg_t,   g_Wsg_t);
    cudaGetSymbolAddress((void**)&Wfg_t,   g_Wfg_t);
    cudaGetSymbolAddress((void**)&Wgate_t, g_Wgate_t);
    cudaGetSymbolAddress((void**)&Wout_t,  g_Wout_t);

    static bool attr_set = false;
    if (!attr_set) {
        cudaFuncSetAttribute(mma_gemm, cudaFuncAttributeMaxDynamicSharedMemorySize, 65536);
        attr_set = true;
    }
    const int SMEM = 65536;

    dim3 tb(32, 8);
    transpose_kernel<<<dim3(PP/32,  IN_D/32),  tb>>>(W_cif,  Wcif_t,  IN_D,  PP);
    transpose_kernel<<<dim3(PP/32,  IN_D/32),  tb>>>(W_csf,  Wcsf_t,  IN_D,  PP);
    transpose_kernel<<<dim3(PP/32,  IMG_D/32), tb>>>(W_cii,  Wcii_t,  IMG_D, PP);
    transpose_kernel<<<dim3(PP/32,  SEM_D/32), tb>>>(W_csn,  Wcsn_t,  SEM_D, PP);
    transpose_kernel<<<dim3(PP/32,  IMG_D/32), tb>>>(W_ig,   Wig_t,   IMG_D, PP);
    transpose_kernel<<<dim3(PP/32,  SEM_D/32), tb>>>(W_sg,   Wsg_t,   SEM_D, PP);
    transpose_kernel<<<dim3(PP/32,  IN_D/32),  tb>>>(W_fg,   Wfg_t,   IN_D,  PP);
    transpose_kernel<<<dim3(CATD/32, CATD/32), tb>>>(W_gate, Wgate_t, CATD,  CATD);
    transpose_kernel<<<dim3(OUTD/32, CATD/32), tb>>>(W_out,  Wout_t,  CATD,  OUTD);

    qproj_kernel<<<dim3(PP/128, BB), 128>>>(que, W_cif + (size_t)IN_D * PP, b_cif, qpi);
    qproj_kernel<<<dim3(PP/128, BB), 128>>>(que, W_csf + (size_t)IN_D * PP, b_csf, qps);

    // np pair (mode 1)
    {
        TaskDesc ta = { h, Wcif_t, nullptr, qpi, npi, IN_D, IN_D, PP, PP, ROWS, IN_D, 1 };
        TaskDesc tb2 = { h, Wcsf_t, nullptr, qps, nps, IN_D, IN_D, PP, PP, ROWS, IN_D, 1 };
        mma_gemm<<<dim3(PP/128, ROWS/128, 2), 256, SMEM>>>(ta, tb2, ta);
    }
    // ip + sp (mode 0)
    {
        TaskDesc ta = { img, Wcii_t, b_cii, nullptr, ipb, IMG_D, IMG_D, 0, PP, BB*NI, IMG_D, 0 };
        TaskDesc tb2 = { sem, Wcsn_t, b_csn, nullptr, spb, SEM_D, SEM_D, 0, PP, BB*SS, SEM_D, 0 };
        mma_gemm<<<dim3(PP/128, 4, 2), 256, SMEM>>>(ta, tb2, ta);
    }

    att_kernel<NI, IMG_D><<<BB * (NN/8), 256>>>(npi, ipb, img, w_ia, ictx);
    att_kernel<SS, SEM_D><<<BB * (NN/8), 256>>>(nps, spb, sem, w_sa, sctx);

    // cat projections (mode 0): f | i | s
    {
        TaskDesc ta = { h,    Wfg_t, b_fg, nullptr, cat,          IN_D,  IN_D,  0, CATD, ROWS, IN_D,  0 };
        TaskDesc tb2 = { ictx, Wig_t, b_ig, nullptr, cat + PP,    IMG_D, IMG_D, 0, CATD, ROWS, IMG_D, 0 };
        TaskDesc tc = { sctx, Wsg_t, b_sg, nullptr, cat + 2*PP,   SEM_D, SEM_D, 0, CATD, ROWS, SEM_D, 0 };
        mma_gemm<<<dim3(PP/128, ROWS/128, 3), 256, SMEM>>>(ta, tb2, tc);
    }
    // gate (mode 2)
    {
        TaskDesc ta = { cat, Wgate_t, b_gate, cat, gcat, CATD, CATD, CATD, CATD, ROWS, CATD, 2 };
        mma_gemm<<<dim3(CATD/128, ROWS/128, 1), 256, SMEM>>>(ta, ta, ta);
    }
    // out (mode 0)
    {
        TaskDesc ta = { gcat, Wout_t, b_out, nullptr, out, CATD, CATD, 0, OUTD, ROWS, CATD, 0 };
        mma_gemm<<<dim3(OUTD/128, ROWS/128, 1), 256, SMEM>>>(ta, ta, ta);
    }
}

// round 4
// speedup vs baseline: 2.5889x; 1.0997x over previous
#include <cuda_runtime.h>
#include <cstdint>

// ---------------- problem dims ----------------
#define BB 8
#define NN 256
#define NI 36
#define SS 64
#define IN_D 1024
#define QUE_D 1024
#define IMG_D 2048
#define SEM_D 512
#define PP 512
#define CATD 1536
#define OUTD 1024
#define ROWS (BB*NN)

// ---------------- scratch ----------------
__device__ float g_qproj_img[BB*PP];
__device__ float g_qproj_sem[BB*PP];
__device__ float g_np_img[ROWS*PP];
__device__ float g_np_sem[ROWS*PP];
__device__ float g_ip[BB*NI*PP];
__device__ float g_sp[BB*SS*PP];
__device__ float g_img_ctx[ROWS*IMG_D];
__device__ float g_sem_ctx[ROWS*SEM_D];
__device__ float g_cat[ROWS*CATD];
__device__ float g_gcat[ROWS*CATD];

// ---------------- helpers ----------------
__device__ __forceinline__ float tanh_fast(float x) {
    float y;
    asm("tanh.approx.f32 %0, %1;" : "=f"(y) : "f"(x));
    return y;
}
__device__ __forceinline__ float sigmoid_fast(float x) {
    return 1.0f / (1.0f + __expf(-x));
}
__device__ __forceinline__ uint32_t f2tf(float x) {
    uint32_t r;
    asm("cvt.rna.tf32.f32 %0, %1;" : "=r"(r) : "f"(x));
    return r;
}
// no volatile, no memory clobber: pure register op, let ptxas schedule freely
__device__ __forceinline__ void mma8(float* c, const uint32_t* a, uint32_t b0, uint32_t b1) {
    asm("mma.sync.aligned.m16n8k8.row.col.f32.tf32.tf32.f32 "
        "{%0,%1,%2,%3}, {%4,%5,%6,%7}, {%8,%9}, {%0,%1,%2,%3};"
        : "+f"(c[0]), "+f"(c[1]), "+f"(c[2]), "+f"(c[3])
        : "r"(a[0]), "r"(a[1]), "r"(a[2]), "r"(a[3]), "r"(b0), "r"(b1));
}

// ---------------- batched tf32 MMA GEMM ----------------
// C[M,N] = A[M,K] @ W[K,N]  (W in NATURAL [K,N] layout, no pre-transpose)
// Epilogue: mode 0: +bias[col]; 1: +extra[(row>>8)*lde+col]; 2: sigmoid(acc+bias)*extra[row*lde+col]
// CTA 128x128, warp tile 64x32 (2x4 warps), K stage 32, double buffered smem.
// A smem: fragment (reg-major) layout, XOR chunk swizzle -> STS.128 and LDS.32 conflict-free.
// B smem: [k][n] rows (128 floats) with chunk swizzle c^=((k&7)<<2) -> coalesced LDG,
//         conflict-free STS.128 phases, 2-way-conflict fragment LDS (acceptable).
struct TaskDesc {
    const float* A; const float* W; const float* bias; const float* extra;
    float* C; int lda, ldw, lde, ldc, M, K, mode;
};

__global__ __launch_bounds__(256)
void mma_gemm(TaskDesc t0, TaskDesc t1, TaskDesc t2) {
    TaskDesc T = (blockIdx.z == 0) ? t0 : (blockIdx.z == 1) ? t1 : t2;
    const int m0 = blockIdx.y * 128;
    if (m0 >= T.M) return;
    const int n0 = blockIdx.x * 128;

    extern __shared__ float sm[];   // 2 stages x (A 4096 | B 4096) floats = 64KB

    const int tid = threadIdx.x;
    const int lane = tid & 31;
    const int wid = tid >> 5;
    const int wr = wid >> 2;        // 0..1
    const int wc = wid & 3;         // 0..3

    // ---- A loader mapping ----
    const int kq   = tid & 7;            // float4 index along k
    const int mrow = tid >> 3;           // base row 0..31 (+32s)
    const int kk_w = kq >> 1;
    const int regA = ((mrow >> 3) & 1) | ((kq & 1) << 1);
    const int chA  = (mrow & 7) ^ kq;
    const float* Ab = T.A + (size_t)(m0 + mrow) * T.lda + kq * 4;
    bool mok[4];
#pragma unroll
    for (int s = 0; s < 4; s++) mok[s] = (m0 + mrow + 32 * s) < T.M;

    // ---- B loader mapping (from natural [K,N]) ----
    const int bk  = tid >> 3;            // k-row 0..31
    const int bcg = tid & 7;             // chunk group (16 floats)
    const float* Wb = T.W + (size_t)bk * T.ldw + n0 + bcg * 16;
    const int bswz = ((bk & 7) << 2);    // chunk XOR

    float acc[4][4][4];
#pragma unroll
    for (int i = 0; i < 4; i++)
#pragma unroll
        for (int t = 0; t < 4; t++)
#pragma unroll
            for (int r = 0; r < 4; r++) acc[i][t][r] = 0.0f;

    float4 avs[4], bvs[4];

    auto store_stage = [&](float* base) {
#pragma unroll
        for (int s = 0; s < 4; s++) {
            int mt = (mrow >> 4) + 2 * s;
            float* pa = base + (((mt * 4 + kk_w) * 4 + regA) << 5) + chA * 4;
            float4 va;
            va.x = __uint_as_float(f2tf(avs[s].x)); va.y = __uint_as_float(f2tf(avs[s].y));
            va.z = __uint_as_float(f2tf(avs[s].z)); va.w = __uint_as_float(f2tf(avs[s].w));
            *(float4*)pa = va;
        }
#pragma unroll
        for (int i = 0; i < 4; i++) {
            int c = bcg * 4 + i;
            float* pb = base + 4096 + bk * 128 + (c ^ bswz) * 4;
            float4 vb;
            vb.x = __uint_as_float(f2tf(bvs[i].x)); vb.y = __uint_as_float(f2tf(bvs[i].y));
            vb.z = __uint_as_float(f2tf(bvs[i].z)); vb.w = __uint_as_float(f2tf(bvs[i].w));
            *(float4*)pb = vb;
        }
    };
    auto fetch_stage = [&](int k0) {
#pragma unroll
        for (int s = 0; s < 4; s++)
            avs[s] = mok[s] ? *(const float4*)(Ab + (size_t)s * 32 * T.lda + k0)
                            : make_float4(0.f, 0.f, 0.f, 0.f);
        const float* wrow = Wb + (size_t)k0 * T.ldw;
#pragma unroll
        for (int i = 0; i < 4; i++)
            bvs[i] = *(const float4*)(wrow + i * 4);
    };

    fetch_stage(0);
    store_stage(sm);
    __syncthreads();

    const int S = T.K >> 5;
    for (int sidx = 0; sidx < S; sidx++) {
        if (sidx + 1 < S) fetch_stage((sidx + 1) << 5);

        {
            const float* base = sm + (size_t)(sidx & 1) * 8192;
#pragma unroll
            for (int kk = 0; kk < 4; kk++) {
                uint32_t a[4][4], b[4][2];
#pragma unroll
                for (int i = 0; i < 4; i++) {
                    int mt = wr * 4 + i;
#pragma unroll
                    for (int r = 0; r < 4; r++) {
                        int chunk = (lane >> 2) ^ (kk * 2 + (r >> 1));
                        a[i][r] = __float_as_uint(
                            base[(((mt * 4 + kk) * 4 + r) << 5) + chunk * 4 + (lane & 3)]);
                    }
                }
#pragma unroll
                for (int t = 0; t < 4; t++) {
                    int nt = wc * 4 + t;
#pragma unroll
                    for (int r = 0; r < 2; r++) {
                        int k = kk * 8 + (lane & 3) + 4 * r;
                        int craw = 2 * nt + (lane >> 4);
                        int cs = craw ^ ((k & 7) << 2);
                        b[t][r] = __float_as_uint(
                            base[4096 + k * 128 + cs * 4 + ((lane >> 2) & 3)]);
                    }
                }
#pragma unroll
                for (int i = 0; i < 4; i++)
#pragma unroll
                    for (int t = 0; t < 4; t++)
                        mma8(acc[i][t], a[i], b[t][0], b[t][1]);
            }
        }

        if (sidx + 1 < S) store_stage(sm + (size_t)((sidx + 1) & 1) * 8192);
        __syncthreads();
    }

    // ---- epilogue ----
#pragma unroll
    for (int i = 0; i < 4; i++) {
        int rbase = m0 + wr * 64 + i * 16 + (lane >> 2);
#pragma unroll
        for (int t = 0; t < 4; t++) {
            int cb = n0 + wc * 32 + t * 8 + 2 * (lane & 3);
#pragma unroll
            for (int hh = 0; hh < 2; hh++) {
                int r = rbase + 8 * hh;
                if (r >= T.M) continue;
                float c0 = acc[i][t][2 * hh], c1 = acc[i][t][2 * hh + 1];
                float2 v;
                if (T.mode == 0) {
                    float2 bs = *(const float2*)(T.bias + cb);
                    v = make_float2(c0 + bs.x, c1 + bs.y);
                } else if (T.mode == 1) {
                    float2 ev = *(const float2*)(T.extra + (size_t)(r >> 8) * T.lde + cb);
                    v = make_float2(c0 + ev.x, c1 + ev.y);
                } else {
                    float2 bs = *(const float2*)(T.bias + cb);
                    float2 ev = *(const float2*)(T.extra + (size_t)r * T.lde + cb);
                    v = make_float2(sigmoid_fast(c0 + bs.x) * ev.x,
                                    sigmoid_fast(c1 + bs.y) * ev.y);
                }
                *(float2*)(T.C + (size_t)r * T.ldc + cb) = v;
            }
        }
    }
}

// ---------------- que projection (both in one launch via z) ----------------
__global__ void qproj_kernel(const float* __restrict__ que,
                             const float* __restrict__ W1, const float* __restrict__ b1,
                             float* __restrict__ o1,
                             const float* __restrict__ W2, const float* __restrict__ b2,
                             float* __restrict__ o2) {
    const float* Wsub = (blockIdx.z == 0) ? W1 : W2;
    const float* bias = (blockIdx.z == 0) ? b1 : b2;
    float* out = (blockIdx.z == 0) ? o1 : o2;
    int b = blockIdx.y;
    int j = blockIdx.x * 128 + threadIdx.x;
    const float* q = que + b * QUE_D;
    float acc = bias[j];
#pragma unroll 4
    for (int k = 0; k < QUE_D; k++) acc += q[k] * Wsub[(size_t)k * PP + j];
    out[b * PP + j] = acc;
}

// ---------------- fused attention: 8 rows per block ----------------
template <int KN, int D>
__global__ __launch_bounds__(256)
void att_kernel(const float* __restrict__ np_, const float* __restrict__ kp,
                const float* __restrict__ kv, const float* __restrict__ w,
                float* __restrict__ ctx) {
    __shared__ __align__(16) float s_w[PP];
    __shared__ float s_logit[8][64];
    __shared__ float s_att[8][64];

    const int g = blockIdx.x;
    const int b = g >> 5;
    const int r0 = (g & 31) * 8;
    const int tid = threadIdx.x;
    const int wid = tid >> 5, lane = tid & 31;

    for (int i = tid; i < PP; i += 256) s_w[i] = w[i];

    const int row = b * NN + r0 + wid;
    float4 npv[4];
    const float4* nr = (const float4*)(np_ + (size_t)row * PP);
#pragma unroll
    for (int i = 0; i < 4; i++) npv[i] = nr[lane + 32 * i];
    __syncthreads();

    for (int k = 0; k < KN; k++) {
        const float4* kr = (const float4*)(kp + (size_t)(b * KN + k) * PP);
        float acc = 0.0f;
#pragma unroll
        for (int i = 0; i < 4; i++) {
            float4 kv4 = kr[lane + 32 * i];
            float4 w4 = ((const float4*)s_w)[lane + 32 * i];
            acc = fmaf(tanh_fast(npv[i].x + kv4.x), w4.x, acc);
            acc = fmaf(tanh_fast(npv[i].y + kv4.y), w4.y, acc);
            acc = fmaf(tanh_fast(npv[i].z + kv4.z), w4.z, acc);
            acc = fmaf(tanh_fast(npv[i].w + kv4.w), w4.w, acc);
        }
#pragma unroll
        for (int o = 16; o > 0; o >>= 1) acc += __shfl_xor_sync(0xffffffff, acc, o);
        if (lane == 0) s_logit[wid][k] = acc;
    }
    __syncwarp();

    {
        float l0 = (lane < KN) ? s_logit[wid][lane] : -1e30f;
        float l1 = (lane + 32 < KN) ? s_logit[wid][lane + 32] : -1e30f;
        float m = fmaxf(l0, l1);
#pragma unroll
        for (int o = 16; o > 0; o >>= 1) m = fmaxf(m, __shfl_xor_sync(0xffffffff, m, o));
        float e0 = (lane < KN) ? __expf(l0 - m) : 0.0f;
        float e1 = (lane + 32 < KN) ? __expf(l1 - m) : 0.0f;
        float sum = e0 + e1;
#pragma unroll
        for (int o = 16; o > 0; o >>= 1) sum += __shfl_xor_sync(0xffffffff, sum, o);
        float inv = 1.0f / sum;
        s_att[wid][lane] = e0 * inv;
        if (lane + 32 < 64) s_att[wid][lane + 32] = e1 * inv;
    }
    __syncthreads();

    const float4* kvb = (const float4*)(kv + (size_t)b * KN * D);
    for (int d4 = tid; d4 < D / 4; d4 += 256) {
        float4 a[8];
#pragma unroll
        for (int r = 0; r < 8; r++) a[r] = make_float4(0.f, 0.f, 0.f, 0.f);
        for (int k = 0; k < KN; k++) {
            float4 v = kvb[(size_t)k * (D / 4) + d4];
#pragma unroll
            for (int r = 0; r < 8; r++) {
                float at = s_att[r][k];
                a[r].x = fmaf(at, v.x, a[r].x);
                a[r].y = fmaf(at, v.y, a[r].y);
                a[r].z = fmaf(at, v.z, a[r].z);
                a[r].w = fmaf(at, v.w, a[r].w);
            }
        }
#pragma unroll
        for (int r = 0; r < 8; r++)
            *(float4*)(ctx + (size_t)(b * NN + r0 + r) * D + d4 * 4) = a[r];
    }
}

// ---------------- launch ----------------
extern "C" void kernel_launch(void* const* d_in, const int* in_sizes, int n_in,
                              void* d_out, int out_size) {
    const float* h      = (const float*)d_in[0];
    const float* img    = (const float*)d_in[1];
    const float* sem    = (const float*)d_in[2];
    const float* que    = (const float*)d_in[3];
    const float* W_cif  = (const float*)d_in[4];
    const float* b_cif  = (const float*)d_in[5];
    const float* W_cii  = (const float*)d_in[6];
    const float* b_cii  = (const float*)d_in[7];
    const float* w_ia   = (const float*)d_in[8];
    const float* W_csf  = (const float*)d_in[10];
    const float* b_csf  = (const float*)d_in[11];
    const float* W_csn  = (const float*)d_in[12];
    const float* b_csn  = (const float*)d_in[13];
    const float* w_sa   = (const float*)d_in[14];
    const float* W_ig   = (const float*)d_in[16];
    const float* b_ig   = (const float*)d_in[17];
    const float* W_sg   = (const float*)d_in[18];
    const float* b_sg   = (const float*)d_in[19];
    const float* W_fg   = (const float*)d_in[20];
    const float* b_fg   = (const float*)d_in[21];
    const float* W_gate = (const float*)d_in[22];
    const float* b_gate = (const float*)d_in[23];
    const float* W_out  = (const float*)d_in[24];
    const float* b_out  = (const float*)d_in[25];
    float* out = (float*)d_out;

    float *qpi, *qps, *npi, *nps, *ipb, *spb, *ictx, *sctx, *cat, *gcat;
    cudaGetSymbolAddress((void**)&qpi,  g_qproj_img);
    cudaGetSymbolAddress((void**)&qps,  g_qproj_sem);
    cudaGetSymbolAddress((void**)&npi,  g_np_img);
    cudaGetSymbolAddress((void**)&nps,  g_np_sem);
    cudaGetSymbolAddress((void**)&ipb,  g_ip);
    cudaGetSymbolAddress((void**)&spb,  g_sp);
    cudaGetSymbolAddress((void**)&ictx, g_img_ctx);
    cudaGetSymbolAddress((void**)&sctx, g_sem_ctx);
    cudaGetSymbolAddress((void**)&cat,  g_cat);
    cudaGetSymbolAddress((void**)&gcat, g_gcat);

    static bool attr_set = false;
    if (!attr_set) {
        cudaFuncSetAttribute(mma_gemm, cudaFuncAttributeMaxDynamicSharedMemorySize, 65536);
        attr_set = true;
    }
    const int SMEM = 65536;

    // 1: que projections (z=2)
    qproj_kernel<<<dim3(PP/128, BB, 2), 128>>>(que, W_cif + (size_t)IN_D * PP, b_cif, qpi,
                                               W_csf + (size_t)IN_D * PP, b_csf, qps);
    // 2: np pair (mode 1)
    {
        TaskDesc ta  = { h, W_cif, nullptr, qpi, npi, IN_D, PP, PP, PP, ROWS, IN_D, 1 };
        TaskDesc tb2 = { h, W_csf, nullptr, qps, nps, IN_D, PP, PP, PP, ROWS, IN_D, 1 };
        mma_gemm<<<dim3(PP/128, ROWS/128, 2), 256, SMEM>>>(ta, tb2, ta);
    }
    // 3: ip + sp (mode 0)
    {
        TaskDesc ta  = { img, W_cii, b_cii, nullptr, ipb, IMG_D, PP, 0, PP, BB*NI, IMG_D, 0 };
        TaskDesc tb2 = { sem, W_csn, b_csn, nullptr, spb, SEM_D, PP, 0, PP, BB*SS, SEM_D, 0 };
        mma_gemm<<<dim3(PP/128, 4, 2), 256, SMEM>>>(ta, tb2, ta);
    }
    // 4,5: fused attention
    att_kernel<NI, IMG_D><<<BB * (NN/8), 256>>>(npi, ipb, img, w_ia, ictx);
    att_kernel<SS, SEM_D><<<BB * (NN/8), 256>>>(nps, spb, sem, w_sa, sctx);
    // 6: cat projections (mode 0): f | i | s
    {
        TaskDesc ta  = { h,    W_fg, b_fg, nullptr, cat,        IN_D,  PP, 0, CATD, ROWS, IN_D,  0 };
        TaskDesc tb2 = { ictx, W_ig, b_ig, nullptr, cat + PP,   IMG_D, PP, 0, CATD, ROWS, IMG_D, 0 };
        TaskDesc tc  = { sctx, W_sg, b_sg, nullptr, cat + 2*PP, SEM_D, PP, 0, CATD, ROWS, SEM_D, 0 };
        mma_gemm<<<dim3(PP/128, ROWS/128, 3), 256, SMEM>>>(ta, tb2, tc);
    }
    // 7: gate (mode 2)
    {
        TaskDesc ta = { cat, W_gate, b_gate, cat, gcat, CATD, CATD, CATD, CATD, ROWS, CATD, 2 };
        mma_gemm<<<dim3(CATD/128, ROWS/128, 1), 256, SMEM>>>(ta, ta, ta);
    }
    // 8: out (mode 0)
    {
        TaskDesc ta = { gcat, W_out, b_out, nullptr, out, CATD, OUTD, 0, OUTD, ROWS, CATD, 0 };
        mma_gemm<<<dim3(OUTD/128, ROWS/128, 1), 256, SMEM>>>(ta, ta, ta);
    }
}

// round 5
// speedup vs baseline: 3.5798x; 1.3827x over previous
#include <cuda_runtime.h>
#include <cstdint>

// ---------------- problem dims ----------------
#define BB 8
#define NN 256
#define NI 36
#define SS 64
#define IN_D 1024
#define QUE_D 1024
#define IMG_D 2048
#define SEM_D 512
#define PP 512
#define CATD 1536
#define OUTD 1024
#define ROWS (BB*NN)

// ---------------- scratch ----------------
__device__ float g_qproj_img[BB*PP];
__device__ float g_qproj_sem[BB*PP];
__device__ float g_np_img[ROWS*PP];
__device__ float g_np_sem[ROWS*PP];
__device__ float g_ip[BB*NI*PP];
__device__ float g_sp[BB*SS*PP];
__device__ float g_img_ctx[ROWS*IMG_D];
__device__ float g_sem_ctx[ROWS*SEM_D];
__device__ float g_cat[ROWS*CATD];
__device__ float g_gcat[ROWS*CATD];
// tf32-pre-rounded copies (GEMM operands)
__device__ float g_h_r[ROWS*IN_D];
__device__ float g_img_r[BB*NI*IMG_D];
__device__ float g_sem_r[BB*SS*SEM_D];
__device__ float g_Wcif_r[IN_D*PP];
__device__ float g_Wcsf_r[IN_D*PP];
__device__ float g_Wcii_r[IMG_D*PP];
__device__ float g_Wcsn_r[SEM_D*PP];
__device__ float g_Wfg_r[IN_D*PP];
__device__ float g_Wig_r[IMG_D*PP];
__device__ float g_Wsg_r[SEM_D*PP];
__device__ float g_Wgate_r[CATD*CATD];
__device__ float g_Wout_r[CATD*OUTD];

// ---------------- helpers ----------------
__device__ __forceinline__ float tanh_fast(float x) {
    float y;
    asm("tanh.approx.f32 %0, %1;" : "=f"(y) : "f"(x));
    return y;
}
__device__ __forceinline__ float sigmoid_fast(float x) {
    return 1.0f / (1.0f + __expf(-x));
}
__device__ __forceinline__ float f2tf_f(float x) {
    uint32_t r;
    asm("cvt.rna.tf32.f32 %0, %1;" : "=r"(r) : "f"(x));
    return __uint_as_float(r);
}
__device__ __forceinline__ void mma8(float* c, const uint32_t* a, uint32_t b0, uint32_t b1) {
    asm("mma.sync.aligned.m16n8k8.row.col.f32.tf32.tf32.f32 "
        "{%0,%1,%2,%3}, {%4,%5,%6,%7}, {%8,%9}, {%0,%1,%2,%3};"
        : "+f"(c[0]), "+f"(c[1]), "+f"(c[2]), "+f"(c[3])
        : "r"(a[0]), "r"(a[1]), "r"(a[2]), "r"(a[3]), "r"(b0), "r"(b1));
}
__device__ __forceinline__ uint32_t smem_u32(const void* p) {
    uint32_t a;
    asm("{ .reg .u64 t; cvta.to.shared.u64 t, %1; cvt.u32.u64 %0, t; }" : "=r"(a) : "l"(p));
    return a;
}
#define CP_ASYNC16(dst, src) \
    asm volatile("cp.async.cg.shared.global [%0], [%1], 16;" :: "r"(dst), "l"(src))
#define CP_COMMIT() asm volatile("cp.async.commit_group;" ::: "memory")
#define CP_WAIT1()  asm volatile("cp.async.wait_group 1;" ::: "memory")

// ---------------- tf32 pre-rounding kernel ----------------
struct CvtList { const float* src[12]; float* dst[12]; int n4[12]; };
__global__ void cvt_prep(CvtList L) {
    int z = blockIdx.y;
    const float4* s = (const float4*)L.src[z];
    float4* d = (float4*)L.dst[z];
    int n4 = L.n4[z];
    for (int i = blockIdx.x * blockDim.x + threadIdx.x; i < n4; i += gridDim.x * blockDim.x) {
        float4 v = s[i];
        v.x = f2tf_f(v.x); v.y = f2tf_f(v.y); v.z = f2tf_f(v.z); v.w = f2tf_f(v.w);
        d[i] = v;
    }
}

// ---------------- batched tf32 MMA GEMM (cp.async 3-stage pipeline) ----------------
// C[M,N] = A[M,K] @ W[K,N]; operands pre-rounded to tf32.
// mode 0: +bias; 1: +extra[(row>>8)*lde+col]; 2: sigmoid(acc+bias)*extra[row*lde+col]
// rnd: round output to tf32 (when it feeds another GEMM).
// CTA 128x128, warp 64x32 (2x4 warps), K stage 32, 3-stage cp.async, 1 sync/stage.
// Smem per stage: A 128x32 row-major (chunk-XOR swizzle), B 32x128 row-major (chunk-XOR).
struct TaskDesc {
    const float* A; const float* W; const float* bias; const float* extra;
    float* C; int lda, ldw, lde, ldc, M, K, mode, rnd;
};

#define STG_FLOATS 8192          // 32KB per stage (A 4096 + B 4096)
#define GEMM_SMEM (3 * STG_FLOATS * 4)

__global__ __launch_bounds__(256, 2)
void mma_gemm(TaskDesc t0, TaskDesc t1, TaskDesc t2) {
    TaskDesc T = (blockIdx.z == 0) ? t0 : (blockIdx.z == 1) ? t1 : t2;
    const int m0 = blockIdx.y * 128;
    if (m0 >= T.M) return;
    const int n0 = blockIdx.x * 128;

    extern __shared__ float sm[];
    const uint32_t smb = smem_u32(sm);

    const int tid = threadIdx.x;
    const int lane = tid & 31;
    const int wid = tid >> 5;
    const int wr = wid >> 2;
    const int wc = wid & 3;

    // ---- loader mappings ----
    const int arow = tid >> 3;             // A row 0..31 (+32s)
    const int ac   = tid & 7;              // A 16B-chunk within row
    const int bk   = tid >> 3;             // B k-row 0..31
    const int bc0  = tid & 7;              // B chunk base (c = bc0+8j)
    // smem dst offsets (bytes, within stage)
    uint32_t adst[4], bdst[4];
#pragma unroll
    for (int s = 0; s < 4; s++) {
        int row = arow + 32 * s;
        adst[s] = (uint32_t)(row * 128 + ((ac ^ (row & 7)) << 4));
    }
#pragma unroll
    for (int j = 0; j < 4; j++) {
        int c = bc0 + 8 * j;
        bdst[j] = (uint32_t)(16384 + bk * 512 + ((c ^ (bk & 7)) << 4));
    }
    // global srcs
    const float* Asrc[4];
#pragma unroll
    for (int s = 0; s < 4; s++) {
        int r = m0 + arow + 32 * s;
        if (r >= T.M) r = T.M - 1;         // clamp; garbage rows discarded in epilogue
        Asrc[s] = T.A + (size_t)r * T.lda + ac * 4;
    }
    const float* Bsrc = T.W + (size_t)bk * T.ldw + n0 + bc0 * 4;

    const int S = T.K >> 5;

    auto issue_stage = [&](int i) {
        uint32_t base = smb + (uint32_t)(i % 3) * (STG_FLOATS * 4);
        int k0 = i << 5;
#pragma unroll
        for (int s = 0; s < 4; s++) CP_ASYNC16(base + adst[s], Asrc[s] + k0);
        const float* wsrc = Bsrc + (size_t)k0 * T.ldw;
#pragma unroll
        for (int j = 0; j < 4; j++) CP_ASYNC16(base + bdst[j], wsrc + 8 * j * 4);
    };

    float acc[4][4][4];
#pragma unroll
    for (int i = 0; i < 4; i++)
#pragma unroll
        for (int t = 0; t < 4; t++)
#pragma unroll
            for (int r = 0; r < 4; r++) acc[i][t][r] = 0.0f;

    issue_stage(0); CP_COMMIT();
    if (S > 1) issue_stage(1);
    CP_COMMIT();

    const int lrow = lane >> 2;            // 0..7
    const int lk   = lane & 3;             // 0..3

    for (int i = 0; i < S; i++) {
        CP_WAIT1();
        __syncthreads();

        const float* base = sm + (size_t)(i % 3) * STG_FLOATS;
#pragma unroll
        for (int kk = 0; kk < 4; kk++) {
            uint32_t a[4][4], b[4][2];
#pragma unroll
            for (int ii = 0; ii < 4; ii++) {
                int mt = wr * 4 + ii;
#pragma unroll
                for (int r = 0; r < 4; r++) {
                    int row = mt * 16 + lrow + 8 * (r & 1);
                    int k = kk * 8 + lk + 4 * (r >> 1);
                    a[ii][r] = __float_as_uint(
                        base[row * 32 + (((k >> 2) ^ (row & 7)) << 2) + (k & 3)]);
                }
            }
#pragma unroll
            for (int t = 0; t < 4; t++) {
                int nt = wc * 4 + t;
#pragma unroll
                for (int r = 0; r < 2; r++) {
                    int k = kk * 8 + lk + 4 * r;
                    int n = nt * 8 + lrow;
                    b[t][r] = __float_as_uint(
                        base[4096 + k * 128 + (((n >> 2) ^ (k & 7)) << 2) + (n & 3)]);
                }
            }
#pragma unroll
            for (int ii = 0; ii < 4; ii++)
#pragma unroll
                for (int t = 0; t < 4; t++)
                    mma8(acc[ii][t], a[ii], b[t][0], b[t][1]);
        }

        if (i + 2 < S) issue_stage(i + 2);
        CP_COMMIT();   // always commit (empty ok) to keep wait_group bookkeeping exact
    }

    // ---- epilogue ----
#pragma unroll
    for (int i = 0; i < 4; i++) {
        int rbase = m0 + wr * 64 + i * 16 + lrow;
#pragma unroll
        for (int t = 0; t < 4; t++) {
            int cb = n0 + wc * 32 + t * 8 + 2 * lk;
#pragma unroll
            for (int hh = 0; hh < 2; hh++) {
                int r = rbase + 8 * hh;
                if (r >= T.M) continue;
                float c0 = acc[i][t][2 * hh], c1 = acc[i][t][2 * hh + 1];
                float2 v;
                if (T.mode == 0) {
                    float2 bs = *(const float2*)(T.bias + cb);
                    v = make_float2(c0 + bs.x, c1 + bs.y);
                } else if (T.mode == 1) {
                    float2 ev = *(const float2*)(T.extra + (size_t)(r >> 8) * T.lde + cb);
                    v = make_float2(c0 + ev.x, c1 + ev.y);
                } else {
                    float2 bs = *(const float2*)(T.bias + cb);
                    float2 ev = *(const float2*)(T.extra + (size_t)r * T.lde + cb);
                    v = make_float2(sigmoid_fast(c0 + bs.x) * ev.x,
                                    sigmoid_fast(c1 + bs.y) * ev.y);
                }
                if (T.rnd) { v.x = f2tf_f(v.x); v.y = f2tf_f(v.y); }
                *(float2*)(T.C + (size_t)r * T.ldc + cb) = v;
            }
        }
    }
}

// ---------------- que projection (fp32 exact) ----------------
__global__ void qproj_kernel(const float* __restrict__ que,
                             const float* __restrict__ W1, const float* __restrict__ b1,
                             float* __restrict__ o1,
                             const float* __restrict__ W2, const float* __restrict__ b2,
                             float* __restrict__ o2) {
    const float* Wsub = (blockIdx.z == 0) ? W1 : W2;
    const float* bias = (blockIdx.z == 0) ? b1 : b2;
    float* out = (blockIdx.z == 0) ? o1 : o2;
    int b = blockIdx.y;
    int j = blockIdx.x * 128 + threadIdx.x;
    const float* q = que + b * QUE_D;
    float acc = bias[j];
#pragma unroll 4
    for (int k = 0; k < QUE_D; k++) acc += q[k] * Wsub[(size_t)k * PP + j];
    out[b * PP + j] = acc;
}

// ---------------- fused attention: 8 rows/block; ctx emitted tf32-rounded ----------------
template <int KN, int D>
__global__ __launch_bounds__(256)
void att_kernel(const float* __restrict__ np_, const float* __restrict__ kp,
                const float* __restrict__ kv, const float* __restrict__ w,
                float* __restrict__ ctx) {
    __shared__ __align__(16) float s_w[PP];
    __shared__ float s_logit[8][64];
    __shared__ float s_att[8][64];

    const int g = blockIdx.x;
    const int b = g >> 5;
    const int r0 = (g & 31) * 8;
    const int tid = threadIdx.x;
    const int wid = tid >> 5, lane = tid & 31;

    for (int i = tid; i < PP; i += 256) s_w[i] = w[i];

    const int row = b * NN + r0 + wid;
    float4 npv[4];
    const float4* nr = (const float4*)(np_ + (size_t)row * PP);
#pragma unroll
    for (int i = 0; i < 4; i++) npv[i] = nr[lane + 32 * i];
    __syncthreads();

    for (int k = 0; k < KN; k++) {
        const float4* kr = (const float4*)(kp + (size_t)(b * KN + k) * PP);
        float acc = 0.0f;
#pragma unroll
        for (int i = 0; i < 4; i++) {
            float4 kv4 = kr[lane + 32 * i];
            float4 w4 = ((const float4*)s_w)[lane + 32 * i];
            acc = fmaf(tanh_fast(npv[i].x + kv4.x), w4.x, acc);
            acc = fmaf(tanh_fast(npv[i].y + kv4.y), w4.y, acc);
            acc = fmaf(tanh_fast(npv[i].z + kv4.z), w4.z, acc);
            acc = fmaf(tanh_fast(npv[i].w + kv4.w), w4.w, acc);
        }
#pragma unroll
        for (int o = 16; o > 0; o >>= 1) acc += __shfl_xor_sync(0xffffffff, acc, o);
        if (lane == 0) s_logit[wid][k] = acc;
    }
    __syncwarp();

    {
        float l0 = (lane < KN) ? s_logit[wid][lane] : -1e30f;
        float l1 = (lane + 32 < KN) ? s_logit[wid][lane + 32] : -1e30f;
        float m = fmaxf(l0, l1);
#pragma unroll
        for (int o = 16; o > 0; o >>= 1) m = fmaxf(m, __shfl_xor_sync(0xffffffff, m, o));
        float e0 = (lane < KN) ? __expf(l0 - m) : 0.0f;
        float e1 = (lane + 32 < KN) ? __expf(l1 - m) : 0.0f;
        float sum = e0 + e1;
#pragma unroll
        for (int o = 16; o > 0; o >>= 1) sum += __shfl_xor_sync(0xffffffff, sum, o);
        float inv = 1.0f / sum;
        s_att[wid][lane] = e0 * inv;
        if (lane + 32 < 64) s_att[wid][lane + 32] = e1 * inv;
    }
    __syncthreads();

    const float4* kvb = (const float4*)(kv + (size_t)b * KN * D);
    for (int d4 = tid; d4 < D / 4; d4 += 256) {
        float4 a[8];
#pragma unroll
        for (int r = 0; r < 8; r++) a[r] = make_float4(0.f, 0.f, 0.f, 0.f);
        for (int k = 0; k < KN; k++) {
            float4 v = kvb[(size_t)k * (D / 4) + d4];
#pragma unroll
            for (int r = 0; r < 8; r++) {
                float at = s_att[r][k];
                a[r].x = fmaf(at, v.x, a[r].x);
                a[r].y = fmaf(at, v.y, a[r].y);
                a[r].z = fmaf(at, v.z, a[r].z);
                a[r].w = fmaf(at, v.w, a[r].w);
            }
        }
#pragma unroll
        for (int r = 0; r < 8; r++) {
            float4 o;
            o.x = f2tf_f(a[r].x); o.y = f2tf_f(a[r].y);
            o.z = f2tf_f(a[r].z); o.w = f2tf_f(a[r].w);
            *(float4*)(ctx + (size_t)(b * NN + r0 + r) * D + d4 * 4) = o;
        }
    }
}

// ---------------- launch ----------------
extern "C" void kernel_launch(void* const* d_in, const int* in_sizes, int n_in,
                              void* d_out, int out_size) {
    const float* h      = (const float*)d_in[0];
    const float* img    = (const float*)d_in[1];
    const float* sem    = (const float*)d_in[2];
    const float* que    = (const float*)d_in[3];
    const float* W_cif  = (const float*)d_in[4];
    const float* b_cif  = (const float*)d_in[5];
    const float* W_cii  = (const float*)d_in[6];
    const float* b_cii  = (const float*)d_in[7];
    const float* w_ia   = (const float*)d_in[8];
    const float* W_csf  = (const float*)d_in[10];
    const float* b_csf  = (const float*)d_in[11];
    const float* W_csn  = (const float*)d_in[12];
    const float* b_csn  = (const float*)d_in[13];
    const float* w_sa   = (const float*)d_in[14];
    const float* W_ig   = (const float*)d_in[16];
    const float* b_ig   = (const float*)d_in[17];
    const float* W_sg   = (const float*)d_in[18];
    const float* b_sg   = (const float*)d_in[19];
    const float* W_fg   = (const float*)d_in[20];
    const float* b_fg   = (const float*)d_in[21];
    const float* W_gate = (const float*)d_in[22];
    const float* b_gate = (const float*)d_in[23];
    const float* W_out  = (const float*)d_in[24];
    const float* b_out  = (const float*)d_in[25];
    float* out = (float*)d_out;

    float *qpi, *qps, *npi, *nps, *ipb, *spb, *ictx, *sctx, *cat, *gcat;
    float *h_r, *img_r, *sem_r;
    float *Wcif_r, *Wcsf_r, *Wcii_r, *Wcsn_r, *Wfg_r, *Wig_r, *Wsg_r, *Wgate_r, *Wout_r;
    cudaGetSymbolAddress((void**)&qpi,  g_qproj_img);
    cudaGetSymbolAddress((void**)&qps,  g_qproj_sem);
    cudaGetSymbolAddress((void**)&npi,  g_np_img);
    cudaGetSymbolAddress((void**)&nps,  g_np_sem);
    cudaGetSymbolAddress((void**)&ipb,  g_ip);
    cudaGetSymbolAddress((void**)&spb,  g_sp);
    cudaGetSymbolAddress((void**)&ictx, g_img_ctx);
    cudaGetSymbolAddress((void**)&sctx, g_sem_ctx);
    cudaGetSymbolAddress((void**)&cat,  g_cat);
    cudaGetSymbolAddress((void**)&gcat, g_gcat);
    cudaGetSymbolAddress((void**)&h_r,    g_h_r);
    cudaGetSymbolAddress((void**)&img_r,  g_img_r);
    cudaGetSymbolAddress((void**)&sem_r,  g_sem_r);
    cudaGetSymbolAddress((void**)&Wcif_r, g_Wcif_r);
    cudaGetSymbolAddress((void**)&Wcsf_r, g_Wcsf_r);
    cudaGetSymbolAddress((void**)&Wcii_r, g_Wcii_r);
    cudaGetSymbolAddress((void**)&Wcsn_r, g_Wcsn_r);
    cudaGetSymbolAddress((void**)&Wfg_r,  g_Wfg_r);
    cudaGetSymbolAddress((void**)&Wig_r,  g_Wig_r);
    cudaGetSymbolAddress((void**)&Wsg_r,  g_Wsg_r);
    cudaGetSymbolAddress((void**)&Wgate_r,g_Wgate_r);
    cudaGetSymbolAddress((void**)&Wout_r, g_Wout_r);

    static bool attr_set = false;
    if (!attr_set) {
        cudaFuncSetAttribute(mma_gemm, cudaFuncAttributeMaxDynamicSharedMemorySize, GEMM_SMEM);
        attr_set = true;
    }

    // 1: pre-round all GEMM operands to tf32
    {
        CvtList L;
        L.src[0] = h;      L.dst[0] = h_r;    L.n4[0] = ROWS*IN_D/4;
        L.src[1] = img;    L.dst[1] = img_r;  L.n4[1] = BB*NI*IMG_D/4;
        L.src[2] = sem;    L.dst[2] = sem_r;  L.n4[2] = BB*SS*SEM_D/4;
        L.src[3] = W_cif;  L.dst[3] = Wcif_r; L.n4[3] = IN_D*PP/4;
        L.src[4] = W_csf;  L.dst[4] = Wcsf_r; L.n4[4] = IN_D*PP/4;
        L.src[5] = W_cii;  L.dst[5] = Wcii_r; L.n4[5] = IMG_D*PP/4;
        L.src[6] = W_csn;  L.dst[6] = Wcsn_r; L.n4[6] = SEM_D*PP/4;
        L.src[7] = W_fg;   L.dst[7] = Wfg_r;  L.n4[7] = IN_D*PP/4;
        L.src[8] = W_ig;   L.dst[8] = Wig_r;  L.n4[8] = IMG_D*PP/4;
        L.src[9] = W_sg;   L.dst[9] = Wsg_r;  L.n4[9] = SEM_D*PP/4;
        L.src[10]= W_gate; L.dst[10]= Wgate_r;L.n4[10]= CATD*CATD/4;
        L.src[11]= W_out;  L.dst[11]= Wout_r; L.n4[11]= CATD*OUTD/4;
        cvt_prep<<<dim3(148, 12), 256>>>(L);
    }
    // 2: que projections (fp32)
    qproj_kernel<<<dim3(PP/128, BB, 2), 128>>>(que, W_cif + (size_t)IN_D * PP, b_cif, qpi,
                                               W_csf + (size_t)IN_D * PP, b_csf, qps);
    // 3: ip + sp
    {
        TaskDesc ta  = { img_r, Wcii_r, b_cii, nullptr, ipb, IMG_D, PP, 0, PP, BB*NI, IMG_D, 0, 0 };
        TaskDesc tb2 = { sem_r, Wcsn_r, b_csn, nullptr, spb, SEM_D, PP, 0, PP, BB*SS, SEM_D, 0, 0 };
        mma_gemm<<<dim3(PP/128, 4, 2), 256, GEMM_SMEM>>>(ta, tb2, ta);
    }
    // 4: np pair  <-- ncu slot (my launch #4)
    {
        TaskDesc ta  = { h_r, Wcif_r, nullptr, qpi, npi, IN_D, PP, PP, PP, ROWS, IN_D, 1, 0 };
        TaskDesc tb2 = { h_r, Wcsf_r, nullptr, qps, nps, IN_D, PP, PP, PP, ROWS, IN_D, 1, 0 };
        mma_gemm<<<dim3(PP/128, ROWS/128, 2), 256, GEMM_SMEM>>>(ta, tb2, ta);
    }
    // 5,6: fused attention (emit tf32-rounded ctx)
    att_kernel<NI, IMG_D><<<BB * (NN/8), 256>>>(npi, ipb, img, w_ia, ictx);
    att_kernel<SS, SEM_D><<<BB * (NN/8), 256>>>(nps, spb, sem, w_sa, sctx);
    // 7: cat projections (rounded outputs feed gate GEMM)
    {
        TaskDesc ta  = { h_r,  Wfg_r, b_fg, nullptr, cat,        IN_D,  PP, 0, CATD, ROWS, IN_D,  0, 1 };
        TaskDesc tb2 = { ictx, Wig_r, b_ig, nullptr, cat + PP,   IMG_D, PP, 0, CATD, ROWS, IMG_D, 0, 1 };
        TaskDesc tc  = { sctx, Wsg_r, b_sg, nullptr, cat + 2*PP, SEM_D, PP, 0, CATD, ROWS, SEM_D, 0, 1 };
        mma_gemm<<<dim3(PP/128, ROWS/128, 3), 256, GEMM_SMEM>>>(ta, tb2, tc);
    }
    // 8: gate (rounded output feeds out GEMM)
    {
        TaskDesc ta = { cat, Wgate_r, b_gate, cat, gcat, CATD, CATD, CATD, CATD, ROWS, CATD, 2, 1 };
        mma_gemm<<<dim3(CATD/128, ROWS/128, 1), 256, GEMM_SMEM>>>(ta, ta, ta);
    }
    // 9: out (fp32 output)
    {
        TaskDesc ta = { gcat, Wout_r, b_out, nullptr, out, CATD, OUTD, 0, OUTD, ROWS, CATD, 0, 0 };
        mma_gemm<<<dim3(OUTD/128, ROWS/128, 1), 256, GEMM_SMEM>>>(ta, ta, ta);
    }
}